// round 1
// baseline (speedup 1.0000x reference)
#include <cuda_runtime.h>
#include <cuda_bf16.h>

#define BATCH 16384
#define DIM   4096
#define DIM4  (DIM / 4)          // 1024 float4 columns
#define TOTAL4 ((size_t)BATCH * DIM4)

__device__ __forceinline__ float apply_act(float x, int f) {
    switch (f) {
        case 0:  return fmaxf(x, 0.0f);                      // relu
        case 1:  return x * (1.0f / (1.0f + __expf(-x)));    // silu
        case 2:  return x > 0.0f ? x : 0.01f * x;            // leaky_relu
        case 3:  return 1.0f / (1.0f + __expf(-x));          // sigmoid
        default: return tanhf(x);                            // tanh
    }
}

__global__ void __launch_bounds__(256)
random_activation_kernel(const float4* __restrict__ x,
                         const float4* __restrict__ max_out,   // [DIM4]
                         const int4*   __restrict__ func_id,   // [DIM4]
                         float4*       __restrict__ out) {
    size_t i = (size_t)blockIdx.x * blockDim.x + threadIdx.x;
    if (i >= TOTAL4) return;

    int c = (int)(i & (DIM4 - 1));   // column-group index, DIM4 is pow2

    float4 xv = x[i];
    int4   f  = func_id[c];
    float4 m  = max_out[c];

    float4 r;
    r.x = fminf(apply_act(xv.x, f.x), m.x);
    r.y = fminf(apply_act(xv.y, f.y), m.y);
    r.z = fminf(apply_act(xv.z, f.z), m.z);
    r.w = fminf(apply_act(xv.w, f.w), m.w);

    out[i] = r;
}

extern "C" void kernel_launch(void* const* d_in, const int* in_sizes, int n_in,
                              void* d_out, int out_size) {
    // metadata order: x (float32 [BATCH*DIM]), max_output (float32 [DIM]),
    //                 func_id (int32 [DIM]); output float32 [BATCH*DIM]
    const float4* x  = (const float4*)d_in[0];
    const float4* mo = (const float4*)d_in[1];
    const int4*   fi = (const int4*)d_in[2];
    float4* out = (float4*)d_out;

    const int threads = 256;
    const int blocks  = (int)((TOTAL4 + threads - 1) / threads);  // 65536
    random_activation_kernel<<<blocks, threads>>>(x, mo, fi, out);
}

// round 2
// speedup vs baseline: 2.4478x; 2.4478x over previous
#include <cuda_runtime.h>
#include <cuda_bf16.h>

#define BATCH 16384
#define DIM   4096
#define DIM4  (DIM / 4)                    // 1024 float4 column-groups
#define TOTAL4 ((size_t)BATCH * DIM4)      // 16,777,216 float4s
#define UNROLL 4
#define THREADS 256
#define BLOCKS  ((int)(TOTAL4 / (THREADS * UNROLL)))   // 16384

// Branchless: compute all 5 activations from shared subexpressions, SEL by f.
__device__ __forceinline__ float act_sel(float x, int f, float m) {
    // e = exp(-x): 1 FMUL + 1 MUFU.EX2
    float e  = __expf(-x);
    // sigmoid: 1 FADD + 1 MUFU.RCP
    float s  = __frcp_rn(1.0f + e);
    float silu = x * s;
    // tanh = (1 - e^2) / (1 + e^2): FMUL + 2 FADD + RCP + FMUL
    float e2 = e * e;
    float th = (1.0f - e2) * __frcp_rn(1.0f + e2);
    float relu  = fmaxf(x, 0.0f);
    float leaky = fmaxf(x, 0.01f * x);     // max(x, 0.01x) == leaky_relu both signs

    float r = relu;                        // f == 0
    r = (f == 1) ? silu  : r;
    r = (f == 2) ? leaky : r;
    r = (f == 3) ? s     : r;
    r = (f == 4) ? th    : r;
    return fminf(r, m);
}

__global__ void __launch_bounds__(THREADS)
random_activation_kernel(const float4* __restrict__ x,
                         const float4* __restrict__ max_out,   // [DIM4]
                         const int4*   __restrict__ func_id,   // [DIM4]
                         float4*       __restrict__ out) {
    size_t tid     = (size_t)blockIdx.x * THREADS + threadIdx.x;
    size_t nthread = (size_t)BLOCKS * THREADS;

    // Front-batch all UNROLL loads for MLP, then compute, then store.
    float4 xv[UNROLL]; int4 fv[UNROLL]; float4 mv[UNROLL]; size_t idx[UNROLL];

#pragma unroll
    for (int k = 0; k < UNROLL; k++) {
        idx[k] = tid + (size_t)k * nthread;
        int c  = (int)(idx[k] & (DIM4 - 1));
        xv[k]  = x[idx[k]];
        fv[k]  = func_id[c];    // L2/L1-hot broadcast
        mv[k]  = max_out[c];
    }

#pragma unroll
    for (int k = 0; k < UNROLL; k++) {
        float4 r;
        r.x = act_sel(xv[k].x, fv[k].x, mv[k].x);
        r.y = act_sel(xv[k].y, fv[k].y, mv[k].y);
        r.z = act_sel(xv[k].z, fv[k].z, mv[k].z);
        r.w = act_sel(xv[k].w, fv[k].w, mv[k].w);
        out[idx[k]] = r;
    }
}

extern "C" void kernel_launch(void* const* d_in, const int* in_sizes, int n_in,
                              void* d_out, int out_size) {
    const float4* x  = (const float4*)d_in[0];
    const float4* mo = (const float4*)d_in[1];
    const int4*   fi = (const int4*)d_in[2];
    float4* out = (float4*)d_out;

    random_activation_kernel<<<BLOCKS, THREADS>>>(x, mo, fi, out);
}

// round 3
// speedup vs baseline: 4.2714x; 1.7450x over previous
#include <cuda_runtime.h>
#include <cuda_bf16.h>

#define BATCH 16384
#define DIM   4096
#define DIM4  (DIM / 4)          // 1024 float4 column-groups
#define THREADS 256
#define CBLK  (DIM4 / THREADS)   // 4 column blocks
#define RPT   16                 // rows per thread
#define RBLK  (BATCH / RPT)      // 1024 row blocks
#define RUN   4                  // row-loop load batch depth

__device__ __forceinline__ float fast_ex2(float x) {
    float r; asm("ex2.approx.f32 %0, %1;" : "=f"(r) : "f"(x)); return r;
}
__device__ __forceinline__ float fast_rcp(float x) {
    float r; asm("rcp.approx.f32 %0, %1;" : "=f"(r) : "f"(x)); return r;
}

struct Coef { float k, b, c, d, g; bool isExp; };

__device__ __forceinline__ Coef make_coef(int f) {
    // exp family: out = (b*x + c) * sigmoid(a*x) + d,  k = -a*log2(e)
    // relu family: out = max(g*x, x)
    const float L2E = 1.4426950408889634f;
    Coef o;
    o.isExp = (f == 1) || (f == 3) || (f == 4);
    o.k = (f == 4) ? -2.0f * L2E : -L2E;
    o.b = (f == 1) ? 1.0f : 0.0f;
    o.c = (f == 3) ? 1.0f : ((f == 4) ? 2.0f : 0.0f);
    o.d = (f == 4) ? -1.0f : 0.0f;
    o.g = (f == 2) ? 0.01f : 0.0f;
    return o;
}

__device__ __forceinline__ float act(float x, const Coef& q, float m) {
    float e   = fast_ex2(q.k * x);           // exp(-a*x)
    float s   = fast_rcp(1.0f + e);          // sigmoid(a*x)
    float eo  = fmaf(fmaf(q.b, x, q.c), s, q.d);
    float ro  = fmaxf(q.g * x, x);
    float r   = q.isExp ? eo : ro;
    return fminf(r, m);
}

__global__ void __launch_bounds__(THREADS)
random_activation_kernel(const float4* __restrict__ x,
                         const float4* __restrict__ max_out,   // [DIM4]
                         const int4*   __restrict__ func_id,   // [DIM4]
                         float4*       __restrict__ out) {
    // Fixed column-group per thread; iterate over RPT rows.
    int c  = blockIdx.x * THREADS + threadIdx.x;     // 0..DIM4-1
    int r0 = blockIdx.y * RPT;

    int4   f = func_id[c];
    float4 m = max_out[c];
    Coef qx = make_coef(f.x);
    Coef qy = make_coef(f.y);
    Coef qz = make_coef(f.z);
    Coef qw = make_coef(f.w);

    size_t base = (size_t)r0 * DIM4 + c;

#pragma unroll
    for (int j0 = 0; j0 < RPT; j0 += RUN) {
        float4 xv[RUN];
        size_t idx[RUN];
#pragma unroll
        for (int j = 0; j < RUN; j++) {
            idx[j] = base + (size_t)(j0 + j) * DIM4;
            xv[j]  = __ldcs(&x[idx[j]]);             // streaming read
        }
#pragma unroll
        for (int j = 0; j < RUN; j++) {
            float4 r;
            r.x = act(xv[j].x, qx, m.x);
            r.y = act(xv[j].y, qy, m.y);
            r.z = act(xv[j].z, qz, m.z);
            r.w = act(xv[j].w, qw, m.w);
            __stcs(&out[idx[j]], r);                 // streaming write
        }
    }
}

extern "C" void kernel_launch(void* const* d_in, const int* in_sizes, int n_in,
                              void* d_out, int out_size) {
    const float4* x  = (const float4*)d_in[0];
    const float4* mo = (const float4*)d_in[1];
    const int4*   fi = (const int4*)d_in[2];
    float4* out = (float4*)d_out;

    dim3 grid(CBLK, RBLK);   // (4, 1024) = 4096 blocks
    random_activation_kernel<<<grid, THREADS>>>(x, mo, fi, out);
}